// round 1
// baseline (speedup 1.0000x reference)
#include <cuda_runtime.h>

#define N_NODES 512
#define HID     1024
#define MG      132          // rows of G = [Hx(128); Ip(4)]
#define KD      4096
#define NE      16384
#define NOUT    513
#define NN      (N_NODES * N_NODES)
#define HPLEN   (N_NODES * HID)   // 524288
#define CH      8
#define CHLEN   (HPLEN / CH)      // 65536

// ---------------- scratch (device globals; no allocation allowed) ----------
__device__ float        g_G[MG * HID];
__device__ float        g_gs1[MG];
__device__ float        g_gs2[MG];
__device__ int          g_winner[NN];
__device__ float        g_P[N_NODES * MG];
__device__ float        g_hp[HPLEN];
__device__ float        g_partial[NOUT * CH];
__device__ unsigned int g_amax_bits;

// ---------------- K0: init ----------------
__global__ void k_init() {
    int i = blockIdx.x * blockDim.x + threadIdx.x;
    int stride = gridDim.x * blockDim.x;
    for (int idx = i; idx < NN; idx += stride) g_winner[idx] = -1;
    for (int idx = i; idx < MG * HID; idx += stride) g_G[idx] = 0.f;
    if (i == 0) g_amax_bits = 0u;
}

// ---------------- K1: G = A(132,4096) @ W(4096,1024), split-K w/ atomics ----
#define BM 64
#define BN 64
#define BK 16
__global__ void __launch_bounds__(256) k_gemm1(const float* __restrict__ X,
                                               const float* __restrict__ img,
                                               const float* __restrict__ W) {
    __shared__ float As[BK][BM];
    __shared__ float Bs[BK][BN];
    int tid = threadIdx.x;
    int bx = blockIdx.x;            // N tile (16)
    int by = blockIdx.y;            // M tile (3)
    int bz = blockIdx.z;            // K split (4) -> 1024 each
    int k0 = bz * 1024;

    int tx = tid & 15, ty = tid >> 4;
    float acc[4][4] = {};

    int a_m  = tid >> 2;            // 0..63
    int a_k4 = (tid & 3) * 4;       // 0,4,8,12
    int b_k  = tid >> 4;            // 0..15
    int b_n4 = (tid & 15) * 4;      // 0..60

    int grow = by * BM + a_m;       // global A row

    for (int kt = 0; kt < 1024; kt += BK) {
        int kg = k0 + kt + a_k4;
        float4 av;
        if (grow < 128) {
            av = *(const float4*)(X + grow * KD + kg);
        } else if (grow < MG) {
            av = *(const float4*)(img + (grow - 128) * 1024 + (kg & 1023));
        } else {
            av = make_float4(0.f, 0.f, 0.f, 0.f);
        }
        int kgb = k0 + kt + b_k;
        float4 bv = *(const float4*)(W + (size_t)kgb * HID + bx * BN + b_n4);

        __syncthreads();
        As[a_k4 + 0][a_m] = av.x;
        As[a_k4 + 1][a_m] = av.y;
        As[a_k4 + 2][a_m] = av.z;
        As[a_k4 + 3][a_m] = av.w;
        *(float4*)&Bs[b_k][b_n4] = bv;
        __syncthreads();

        #pragma unroll
        for (int k = 0; k < BK; k++) {
            float4 a4 = *(float4*)&As[k][ty * 4];
            float4 b4 = *(float4*)&Bs[k][tx * 4];
            float ar[4] = {a4.x, a4.y, a4.z, a4.w};
            float br[4] = {b4.x, b4.y, b4.z, b4.w};
            #pragma unroll
            for (int i = 0; i < 4; i++)
                #pragma unroll
                for (int j = 0; j < 4; j++)
                    acc[i][j] += ar[i] * br[j];
        }
    }

    #pragma unroll
    for (int i = 0; i < 4; i++) {
        int r = by * BM + ty * 4 + i;
        if (r < MG) {
            #pragma unroll
            for (int j = 0; j < 4; j++)
                atomicAdd(&g_G[r * HID + bx * BN + tx * 4 + j], acc[i][j]);
        }
    }
}

// ---------------- K2: gs1/gs2 = G row dots with a ----------------
__global__ void k_gs(const float* __restrict__ a) {
    int m = blockIdx.x;
    int t = threadIdx.x;            // 256
    const float* g = g_G + m * HID;
    float s1 = 0.f, s2 = 0.f;
    for (int i = t; i < HID; i += 256) {
        float v = g[i];
        s1 += v * a[i];
        s2 += v * a[HID + i];
    }
    __shared__ float sh1[256], sh2[256];
    sh1[t] = s1; sh2[t] = s2;
    __syncthreads();
    for (int s = 128; s > 0; s >>= 1) {
        if (t < s) { sh1[t] += sh1[t + s]; sh2[t] += sh2[t + s]; }
        __syncthreads();
    }
    if (t == 0) { g_gs1[m] = sh1[0]; g_gs2[m] = sh2[0]; }
}

// ---------------- K3: scatter winners (last edge wins) + amax --------------
__global__ void k_scatter(const int* __restrict__ er, const int* __restrict__ ec) {
    int e = blockIdx.x * blockDim.x + threadIdx.x;
    if (e < NE) atomicMax(&g_winner[er[e] * N_NODES + ec[e]], e);
}
__global__ void k_amax(const int* __restrict__ er, const int* __restrict__ ec,
                       const float* __restrict__ av) {
    int e = blockIdx.x * blockDim.x + threadIdx.x;
    if (e < NE && g_winner[er[e] * N_NODES + ec[e]] == e)
        atomicMax(&g_amax_bits, __float_as_uint(av[e]));   // av >= 0
}

// ---------------- K4: per-row softmax + new_adj + P ----------------
__global__ void __launch_bounds__(128) k_row(const float* __restrict__ adj_vals,
                                             float* __restrict__ out) {
    int r = blockIdx.x;
    int t = threadIdx.x;            // 128
    __shared__ float red[128];

    float s1r = g_gs1[r & 127] + g_gs1[128 + (r >> 7)];

    float ev[4]; int w[4];
    float lmax = -1e30f;
    #pragma unroll
    for (int j = 0; j < 4; j++) {
        int c = t + 128 * j;
        float s2c = g_gs2[c & 127] + g_gs2[128 + j];
        int ww = g_winner[r * N_NODES + c];
        w[j] = ww;
        float x = 0.f;
        if (ww >= 0) { float v = s1r + s2c; x = v > 0.f ? v : 0.2f * v; }
        ev[j] = x;
        lmax = fmaxf(lmax, x);
    }
    red[t] = lmax; __syncthreads();
    for (int s = 64; s > 0; s >>= 1) {
        if (t < s) red[t] = fmaxf(red[t], red[t + s]);
        __syncthreads();
    }
    float rmax = red[0]; __syncthreads();

    float ex[4]; float lsum = 0.f;
    #pragma unroll
    for (int j = 0; j < 4; j++) { ex[j] = expf(ev[j] - rmax); lsum += ex[j]; }
    red[t] = lsum; __syncthreads();
    for (int s = 64; s > 0; s >>= 1) {
        if (t < s) red[t] += red[t + s];
        __syncthreads();
    }
    float inv = 1.f / red[0]; __syncthreads();

    float amax2 = 2.f * __uint_as_float(g_amax_bits);
    float invA = amax2 > 0.f ? 1.f / amax2 : 0.f;

    float attj[4]; float pm = 0.f;
    #pragma unroll
    for (int j = 0; j < 4; j++) {
        float att = ex[j] * inv;
        attj[j] = att;
        float adjn = (w[j] >= 0) ? (2.f * adj_vals[w[j]]) * invA : 0.f;
        out[r * N_NODES + t + 128 * j] = att * adjn;
        pm += att;
    }
    g_P[r * MG + t] = pm;          // c & 127 == t for all 4 cols

    #pragma unroll
    for (int j = 0; j < 4; j++) {  // column-block sums -> P[r, 128+j]
        red[t] = attj[j]; __syncthreads();
        for (int s = 64; s > 0; s >>= 1) {
            if (t < s) red[t] += red[t + s];
            __syncthreads();
        }
        if (t == 0) g_P[r * MG + 128 + j] = red[0];
        __syncthreads();
    }
}

// ---------------- K5: hp = P(512,132) @ G(132,1024) ----------------
__global__ void __launch_bounds__(256) k_hp() {
    __shared__ float Ps[32][MG];
    __shared__ float Gs[MG][32];
    int bx = blockIdx.x;            // col tile (32)
    int by = blockIdx.y;            // row tile (16)
    int tid = threadIdx.x;

    for (int i = tid; i < 32 * MG; i += 256) {
        int rr = i / MG, kk = i % MG;
        Ps[rr][kk] = g_P[(by * 32 + rr) * MG + kk];
    }
    for (int i = tid; i < MG * 32; i += 256) {
        int kk = i / 32, cc = i % 32;
        Gs[kk][cc] = g_G[kk * HID + bx * 32 + cc];
    }
    __syncthreads();

    int tx = tid & 7, ty = tid >> 3;   // ty: row 0..31, tx: col4 0..7
    float4 acc = make_float4(0.f, 0.f, 0.f, 0.f);
    #pragma unroll 4
    for (int k = 0; k < MG; k++) {
        float p = Ps[ty][k];
        float4 gv = *(float4*)&Gs[k][tx * 4];
        acc.x += p * gv.x; acc.y += p * gv.y;
        acc.z += p * gv.z; acc.w += p * gv.w;
    }
    int row = by * 32 + ty, col = bx * 32 + tx * 4;
    *(float4*)&g_hp[row * HID + col] = acc;
}

// ---------------- K6: out_partial = lin_w(513,524288) @ hp ----------------
__global__ void __launch_bounds__(256) k_gemv(const float* __restrict__ lin_w) {
    int chunk = blockIdx.x;
    int row = blockIdx.y;
    int t = threadIdx.x;            // 256
    const float* wp = lin_w + (size_t)row * HPLEN + (size_t)chunk * CHLEN;
    const float* vp = g_hp + chunk * CHLEN;
    float acc = 0.f;
    #pragma unroll 4
    for (int i = t * 4; i < CHLEN; i += 1024) {
        float4 w4 = *(const float4*)(wp + i);
        float4 v4 = *(const float4*)(vp + i);
        acc += w4.x * v4.x + w4.y * v4.y + w4.z * v4.z + w4.w * v4.w;
    }
    __shared__ float sh[256];
    sh[t] = acc; __syncthreads();
    for (int s = 128; s > 0; s >>= 1) {
        if (t < s) sh[t] += sh[t + s];
        __syncthreads();
    }
    if (t == 0) g_partial[row * CH + chunk] = sh[0];
}

// ---------------- K7: finalize + min/max normalize ----------------
__global__ void k_final(const float* __restrict__ lin_b, float* __restrict__ out) {
    __shared__ float vals[NOUT];
    __shared__ float smin[256], smax[256];
    int t = threadIdx.x;            // 256
    for (int i = t; i < NOUT; i += 256) {
        float s = lin_b[i];
        #pragma unroll
        for (int c = 0; c < CH; c++) s += g_partial[i * CH + c];
        vals[i] = s;
    }
    __syncthreads();
    float mn = 1e30f, mx = -1e30f;
    for (int i = t; i < NOUT; i += 256) {
        mn = fminf(mn, vals[i]);
        mx = fmaxf(mx, vals[i]);
    }
    smin[t] = mn; smax[t] = mx; __syncthreads();
    for (int s = 128; s > 0; s >>= 1) {
        if (t < s) {
            smin[t] = fminf(smin[t], smin[t + s]);
            smax[t] = fmaxf(smax[t], smax[t + s]);
        }
        __syncthreads();
    }
    float gmn = smin[0], gmx = smax[0];
    float denom = gmx - gmn;
    for (int i = t; i < NOUT; i += 256)
        out[NN + i] = (denom == 0.f) ? 0.5f : (vals[i] - gmn) / denom;
}

// ---------------- launch ----------------
extern "C" void kernel_launch(void* const* d_in, const int* in_sizes, int n_in,
                              void* d_out, int out_size) {
    const float* img = (const float*)d_in[0];
    const int*   er  = (const int*)d_in[1];
    const int*   ec  = (const int*)d_in[2];
    const float* av  = (const float*)d_in[3];
    const float* X   = (const float*)d_in[4];
    const float* W   = (const float*)d_in[5];
    const float* a   = (const float*)d_in[6];
    const float* lw  = (const float*)d_in[7];
    const float* lb  = (const float*)d_in[8];
    float* out = (float*)d_out;

    k_init<<<256, 256>>>();
    dim3 g1(16, 3, 4);
    k_gemm1<<<g1, 256>>>(X, img, W);
    k_gs<<<MG, 256>>>(a);
    k_scatter<<<64, 256>>>(er, ec);
    k_amax<<<64, 256>>>(er, ec, av);
    k_row<<<512, 128>>>(av, out);
    dim3 g5(32, 16);
    k_hp<<<g5, 256>>>();
    dim3 g6(CH, NOUT);
    k_gemv<<<g6, 256>>>(lw);
    k_final<<<1, 256>>>(lb, out);
}